// round 6
// baseline (speedup 1.0000x reference)
#include <cuda_runtime.h>
#include <cstdint>

// Problem constants: B=512, T=256, C=384, HS=16
#define TT   256
#define CC   384
#define HSZ  16
#define KCH  32          // K-chunk for projection
#define NKC  (CC/KCH)    // 12
#define XP1  36          // x tile row stride (floats)
#define WSP  56          // W tile row stride
#define QKP  20          // q/k row stride
#define VPD  24          // v row stride

// smem (floats):
//  phase1: 2 x (256*36 + 32*56) = 22016 f = 88064 B  (max)
//  phase2: q[256*20] k[256*20] v[256*24] psumA[8*256] rinvG[256] = 18688 f
#define SMEM_FLOATS (2 * (TT * XP1 + KCH * WSP))
#define SMEM_BYTES  (SMEM_FLOATS * 4)

__device__ __forceinline__ unsigned f2tf(float f) {
    unsigned r;
    asm("cvt.rna.tf32.f32 %0, %1;" : "=r"(r) : "f"(f));
    return r;
}

__device__ __forceinline__ void mma_tf32(float* c, const unsigned* a, const unsigned* b) {
    asm volatile(
        "mma.sync.aligned.m16n8k8.row.col.f32.tf32.tf32.f32 "
        "{%0,%1,%2,%3}, {%4,%5,%6,%7}, {%8,%9}, {%0,%1,%2,%3};"
        : "+f"(c[0]), "+f"(c[1]), "+f"(c[2]), "+f"(c[3])
        : "r"(a[0]), "r"(a[1]), "r"(a[2]), "r"(a[3]), "r"(b[0]), "r"(b[1]));
}

__device__ __forceinline__ void cpa16(uint32_t saddr, const float* g) {
    asm volatile("cp.async.ca.shared.global [%0], [%1], 16;" :: "r"(saddr), "l"(g));
}

__global__ void __launch_bounds__(256, 2) head_fused_kernel(
    const float* __restrict__ x,
    const float* __restrict__ wk,
    const float* __restrict__ wq,
    const float* __restrict__ wv,
    float* __restrict__ out)
{
    extern __shared__ float sm[];
    const int b    = blockIdx.x;
    const int tid  = threadIdx.x;
    const int lane = tid & 31;
    const int warp = tid >> 5;
    const int grp  = lane >> 2;  // 0..7
    const int tig  = lane & 3;   // 0..3

    const uint32_t sm_base = (uint32_t)__cvta_generic_to_shared(sm);

    // phase-2 smem views
    float* q_s   = sm;
    float* k_s   = q_s + TT * QKP;
    float* v_s   = k_s + TT * QKP;
    float* psumA = v_s + TT * VPD;      // [8 warps][256 cols]
    float* rinvG = psumA + 8 * 256;     // [256]

    const float* xb = x + (size_t)b * TT * CC;

    // ================= Phase 1: qkv = x @ [Wq|Wk|Wv] =================
    // x: cp.async raw, tf32 hi/lo split at fragment time (2-term). W: pre-tf32 STS.
    const int R = warp * 32;

    float acc[2][6][4];
#pragma unroll
    for (int mt = 0; mt < 2; ++mt)
#pragma unroll
        for (int nt = 0; nt < 6; ++nt)
#pragma unroll
            for (int e = 0; e < 4; ++e) acc[mt][nt][e] = 0.f;

    auto load_chunk = [&](int kc, int buf) {
        const float* xg = xb + kc * KCH;
        uint32_t xs_a = sm_base + (uint32_t)(buf * TT * XP1) * 4u;
#pragma unroll
        for (int i = 0; i < 8; ++i) {
            int row = (tid >> 3) + i * 32;
            int c4  = (tid & 7) * 4;
            cpa16(xs_a + (uint32_t)(row * XP1 + c4) * 4u, xg + row * CC + c4);
        }
        float* wsd = sm + 2 * TT * XP1 + buf * KCH * WSP;
#pragma unroll
        for (int i = 0; i < 2; ++i) {
            int f = tid + i * 256;
            if (f < KCH * 12) {
                int rowk = f / 12, c4 = f % 12;
                int gk = kc * KCH + rowk;
                const float* src = (c4 < 4) ? (wq + gk * HSZ + c4 * 4)
                                 : (c4 < 8) ? (wk + gk * HSZ + (c4 - 4) * 4)
                                            : (wv + gk * HSZ + (c4 - 8) * 4);
                float4 w4 = *reinterpret_cast<const float4*>(src);
                float4 t4;
                t4.x = __uint_as_float(f2tf(w4.x));
                t4.y = __uint_as_float(f2tf(w4.y));
                t4.z = __uint_as_float(f2tf(w4.z));
                t4.w = __uint_as_float(f2tf(w4.w));
                *reinterpret_cast<float4*>(wsd + rowk * WSP + c4 * 4) = t4;
            }
        }
    };

    load_chunk(0, 0);
    asm volatile("cp.async.commit_group;");

    for (int kc = 0; kc < NKC; ++kc) {
        const int buf = kc & 1;
        if (kc + 1 < NKC) {
            load_chunk(kc + 1, buf ^ 1);
            asm volatile("cp.async.commit_group;");
            asm volatile("cp.async.wait_group 1;");
        } else {
            asm volatile("cp.async.wait_group 0;");
        }
        __syncthreads();

        const float* xs = sm + buf * TT * XP1;
        const float* ws = sm + 2 * TT * XP1 + buf * KCH * WSP;

#pragma unroll
        for (int k8 = 0; k8 < 4; ++k8) {
            const int ko = k8 * 8;
            unsigned ah[2][4], al[2][4];
#pragma unroll
            for (int mt = 0; mt < 2; ++mt) {
                int r0 = R + mt * 16 + grp;
                float v0 = xs[r0 * XP1 + ko + tig];
                float v1 = xs[(r0 + 8) * XP1 + ko + tig];
                float v2 = xs[r0 * XP1 + ko + tig + 4];
                float v3 = xs[(r0 + 8) * XP1 + ko + tig + 4];
                ah[mt][0] = f2tf(v0); al[mt][0] = f2tf(v0 - __uint_as_float(ah[mt][0]));
                ah[mt][1] = f2tf(v1); al[mt][1] = f2tf(v1 - __uint_as_float(ah[mt][1]));
                ah[mt][2] = f2tf(v2); al[mt][2] = f2tf(v2 - __uint_as_float(ah[mt][2]));
                ah[mt][3] = f2tf(v3); al[mt][3] = f2tf(v3 - __uint_as_float(ah[mt][3]));
            }
#pragma unroll
            for (int nt = 0; nt < 6; ++nt) {
                int cb = nt * 8 + grp;
                unsigned bh[2];
                bh[0] = __float_as_uint(ws[(ko + tig) * WSP + cb]);      // pre-tf32
                bh[1] = __float_as_uint(ws[(ko + tig + 4) * WSP + cb]);  // pre-tf32
#pragma unroll
                for (int mt = 0; mt < 2; ++mt) {
                    mma_tf32(acc[mt][nt], ah[mt], bh);
                    mma_tf32(acc[mt][nt], al[mt], bh);
                }
            }
        }
        __syncthreads();
    }

    // scatter qkv; q (scaled) and k pre-rounded to tf32; v raw fp32
    const float qscale = rsqrtf((float)CC);
#pragma unroll
    for (int mt = 0; mt < 2; ++mt)
#pragma unroll
        for (int nt = 0; nt < 6; ++nt)
#pragma unroll
            for (int e = 0; e < 4; ++e) {
                int r   = R + mt * 16 + grp + ((e >= 2) ? 8 : 0);
                int cgl = nt * 8 + 2 * tig + (e & 1);
                float v = acc[mt][nt][e];
                if (cgl < 16)      q_s[r * QKP + cgl]        = __uint_as_float(f2tf(v * qscale));
                else if (cgl < 32) k_s[r * QKP + (cgl - 16)] = __uint_as_float(f2tf(v));
                else               v_s[r * VPD + (cgl - 32)] = v;
            }
    __syncthreads();

    // ================= Phase 2: column softmax, two barrier-free passes ==========
    const int rb0 = warp * 16;
    const int rb1 = 240 - warp * 16;
    int rb[2] = {rb0, rb1};

    // ---------- Pass A: denominators (no barriers inside loop) ----------
    for (int blk = 0; blk < TT / 32; ++blk) {
        const int s0 = blk * 32;
        const bool act0 = (warp >= 2 * blk);
        const bool act1 = ((15 - warp) >= 2 * blk);
        const bool anyact = act1;

        float ps[4][2];
#pragma unroll
        for (int nt = 0; nt < 4; ++nt) { ps[nt][0] = 0.f; ps[nt][1] = 0.f; }

        if (anyact) {
            float ef[2][4][4];
#pragma unroll
            for (int mt = 0; mt < 2; ++mt)
#pragma unroll
                for (int nt = 0; nt < 4; ++nt)
#pragma unroll
                    for (int e = 0; e < 4; ++e) ef[mt][nt][e] = 0.f;
#pragma unroll
            for (int k8 = 0; k8 < 2; ++k8) {
                const int ko = k8 * 8;
                unsigned aq[2][4];
#pragma unroll
                for (int mt = 0; mt < 2; ++mt) {
                    if (mt == 0 && !act0) continue;
                    int r0 = rb[mt] + grp;
                    aq[mt][0] = __float_as_uint(q_s[r0 * QKP + ko + tig]);
                    aq[mt][1] = __float_as_uint(q_s[(r0 + 8) * QKP + ko + tig]);
                    aq[mt][2] = __float_as_uint(q_s[r0 * QKP + ko + tig + 4]);
                    aq[mt][3] = __float_as_uint(q_s[(r0 + 8) * QKP + ko + tig + 4]);
                }
#pragma unroll
                for (int nt = 0; nt < 4; ++nt) {
                    int sc = s0 + nt * 8 + grp;
                    unsigned bb[2];
                    bb[0] = __float_as_uint(k_s[sc * QKP + ko + tig]);
                    bb[1] = __float_as_uint(k_s[sc * QKP + ko + tig + 4]);
                    if (act0) mma_tf32(ef[0][nt], aq[0], bb);
                    mma_tf32(ef[1][nt], aq[1], bb);
                }
            }
#pragma unroll
            for (int mt = 0; mt < 2; ++mt) {
                if (mt == 0 && !act0) {
#pragma unroll
                    for (int nt = 0; nt < 4; ++nt)
#pragma unroll
                        for (int e = 0; e < 4; ++e) ef[0][nt][e] = 0.f;
                    continue;
                }
#pragma unroll
                for (int nt = 0; nt < 4; ++nt)
#pragma unroll
                    for (int e = 0; e < 4; ++e) {
                        int r  = rb[mt] + grp + ((e >= 2) ? 8 : 0);
                        int sg = s0 + nt * 8 + 2 * tig + (e & 1);
                        ef[mt][nt][e] = (sg <= r) ? __expf(ef[mt][nt][e]) : 0.f;
                    }
            }
#pragma unroll
            for (int nt = 0; nt < 4; ++nt)
#pragma unroll
                for (int bb2 = 0; bb2 < 2; ++bb2) {
                    float s = ef[0][nt][bb2] + ef[0][nt][bb2 + 2]
                            + ef[1][nt][bb2] + ef[1][nt][bb2 + 2];
                    s += __shfl_xor_sync(0xffffffffu, s, 4);
                    s += __shfl_xor_sync(0xffffffffu, s, 8);
                    s += __shfl_xor_sync(0xffffffffu, s, 16);
                    ps[nt][bb2] = s;
                }
        }
        if (grp == 0) {   // unconditional per-blk write: covers all 256 columns
#pragma unroll
            for (int nt = 0; nt < 4; ++nt) {
                psumA[warp * 256 + s0 + nt * 8 + 2 * tig]     = ps[nt][0];
                psumA[warp * 256 + s0 + nt * 8 + 2 * tig + 1] = ps[nt][1];
            }
        }
    }
    __syncthreads();
    // cooperative reduce: thread t owns column t
    {
        float tot = 0.f;
#pragma unroll
        for (int w = 0; w < 8; ++w) tot += psumA[w * 256 + tid];
        rinvG[tid] = 1.0f / tot;
    }
    __syncthreads();

    // ---------- Pass B: output (completely barrier-free) ----------
    float oacc[2][2][4];
#pragma unroll
    for (int mt = 0; mt < 2; ++mt)
#pragma unroll
        for (int nt = 0; nt < 2; ++nt)
#pragma unroll
            for (int e = 0; e < 4; ++e) oacc[mt][nt][e] = 0.f;

    for (int blk = 0; blk < TT / 32; ++blk) {
        const int s0 = blk * 32;
        const bool act0 = (warp >= 2 * blk);
        const bool act1 = ((15 - warp) >= 2 * blk);
        if (!act1) continue;

        float ef[2][4][4];
#pragma unroll
        for (int mt = 0; mt < 2; ++mt)
#pragma unroll
            for (int nt = 0; nt < 4; ++nt)
#pragma unroll
                for (int e = 0; e < 4; ++e) ef[mt][nt][e] = 0.f;

        // S = q k^T (pre-tf32 operands)
#pragma unroll
        for (int k8 = 0; k8 < 2; ++k8) {
            const int ko = k8 * 8;
            unsigned aq[2][4];
#pragma unroll
            for (int mt = 0; mt < 2; ++mt) {
                if (mt == 0 && !act0) continue;
                int r0 = rb[mt] + grp;
                aq[mt][0] = __float_as_uint(q_s[r0 * QKP + ko + tig]);
                aq[mt][1] = __float_as_uint(q_s[(r0 + 8) * QKP + ko + tig]);
                aq[mt][2] = __float_as_uint(q_s[r0 * QKP + ko + tig + 4]);
                aq[mt][3] = __float_as_uint(q_s[(r0 + 8) * QKP + ko + tig + 4]);
            }
#pragma unroll
            for (int nt = 0; nt < 4; ++nt) {
                int sc = s0 + nt * 8 + grp;
                unsigned bb[2];
                bb[0] = __float_as_uint(k_s[sc * QKP + ko + tig]);
                bb[1] = __float_as_uint(k_s[sc * QKP + ko + tig + 4]);
                if (act0) mma_tf32(ef[0][nt], aq[0], bb);
                mma_tf32(ef[1][nt], aq[1], bb);
            }
        }
        // mask + exp
#pragma unroll
        for (int mt = 0; mt < 2; ++mt) {
            if (mt == 0 && !act0) {
#pragma unroll
                for (int nt = 0; nt < 4; ++nt)
#pragma unroll
                    for (int e = 0; e < 4; ++e) ef[0][nt][e] = 0.f;
                continue;
            }
#pragma unroll
            for (int nt = 0; nt < 4; ++nt)
#pragma unroll
                for (int e = 0; e < 4; ++e) {
                    int r  = rb[mt] + grp + ((e >= 2) ? 8 : 0);
                    int sg = s0 + nt * 8 + 2 * tig + (e & 1);
                    ef[mt][nt][e] = (sg <= r) ? __expf(ef[mt][nt][e]) : 0.f;
                }
        }

        // rinv for this block's 32 columns: lane L -> col s0+L (conflict-free LDS)
        float rv = rinvG[s0 + lane];

        // PV: oacc += P @ (rinv[s]*v), P single tf32, v split (2-term)
        const int src1 = grp * 4 + (tig >> 1);
        const int src2 = src1 + 2;
        const int sel  = tig & 1;
#pragma unroll
        for (int k8 = 0; k8 < 4; ++k8) {
            const int ko = k8 * 8;
            float rv0 = __shfl_sync(0xffffffffu, rv, ko + tig);
            float rv1 = __shfl_sync(0xffffffffu, rv, ko + tig + 4);
            unsigned ph[2][4];
#pragma unroll
            for (int mt = 0; mt < 2; ++mt) {
                if (mt == 0 && !act0) continue;
                float s0v = __shfl_sync(0xffffffffu, ef[mt][k8][0], src1);
                float s1v = __shfl_sync(0xffffffffu, ef[mt][k8][1], src1);
                float s2v = __shfl_sync(0xffffffffu, ef[mt][k8][2], src1);
                float s3v = __shfl_sync(0xffffffffu, ef[mt][k8][3], src1);
                float t0v = __shfl_sync(0xffffffffu, ef[mt][k8][0], src2);
                float t1v = __shfl_sync(0xffffffffu, ef[mt][k8][1], src2);
                float t2v = __shfl_sync(0xffffffffu, ef[mt][k8][2], src2);
                float t3v = __shfl_sync(0xffffffffu, ef[mt][k8][3], src2);
                ph[mt][0] = f2tf(sel ? s1v : s0v);
                ph[mt][1] = f2tf(sel ? s3v : s2v);
                ph[mt][2] = f2tf(sel ? t1v : t0v);
                ph[mt][3] = f2tf(sel ? t3v : t2v);
            }
#pragma unroll
            for (int nt = 0; nt < 2; ++nt) {
                int d = nt * 8 + grp;
                float vv0 = v_s[(s0 + ko + tig) * VPD + d]     * rv0;
                float vv1 = v_s[(s0 + ko + tig + 4) * VPD + d] * rv1;
                unsigned bh[2], bl[2];
                bh[0] = f2tf(vv0); bl[0] = f2tf(vv0 - __uint_as_float(bh[0]));
                bh[1] = f2tf(vv1); bl[1] = f2tf(vv1 - __uint_as_float(bh[1]));
                if (act0) {
                    mma_tf32(oacc[0][nt], ph[0], bh);
                    mma_tf32(oacc[0][nt], ph[0], bl);
                }
                mma_tf32(oacc[1][nt], ph[1], bh);
                mma_tf32(oacc[1][nt], ph[1], bl);
            }
        }
    }

    // ---- write out[b, t, d] ----
    float* ob = out + (size_t)b * TT * HSZ;
#pragma unroll
    for (int mt = 0; mt < 2; ++mt)
#pragma unroll
        for (int nt = 0; nt < 2; ++nt) {
            int r0 = rb[mt] + grp;
            int c  = nt * 8 + 2 * tig;
            *reinterpret_cast<float2*>(ob + r0 * HSZ + c) =
                make_float2(oacc[mt][nt][0], oacc[mt][nt][1]);
            *reinterpret_cast<float2*>(ob + (r0 + 8) * HSZ + c) =
                make_float2(oacc[mt][nt][2], oacc[mt][nt][3]);
        }
}

extern "C" void kernel_launch(void* const* d_in, const int* in_sizes, int n_in,
                              void* d_out, int out_size) {
    const float* x  = (const float*)d_in[0];
    const float* wk = (const float*)d_in[1];
    const float* wq = (const float*)d_in[2];
    const float* wv = (const float*)d_in[3];
    float* out      = (float*)d_out;

    const int B = in_sizes[0] / (TT * CC);  // 512

    cudaFuncSetAttribute(head_fused_kernel,
                         cudaFuncAttributeMaxDynamicSharedMemorySize, SMEM_BYTES);
    head_fused_kernel<<<B, 256, SMEM_BYTES>>>(x, wk, wq, wv, out);
}

// round 7
// speedup vs baseline: 1.1527x; 1.1527x over previous
#include <cuda_runtime.h>
#include <cstdint>

// Problem constants: B=512, T=256, C=384, HS=16
#define TT   256
#define CC   384
#define HSZ  16
#define KCH  32          // K-chunk for projection
#define NKC  (CC/KCH)    // 12
#define XP1  36          // x tile row stride (floats), even for float2 loads
#define WSP  56          // W packed tile row stride (words), conflict-free
#define QKP  20          // q/k row stride
#define VPD  28          // v row stride (conflict-free for 2*tig-strided reads)

// smem (floats/words):
//  phase1: 2 x (256*36 + 2*16*56) = 22016 = 88064 B  (max)
//  phase2: q[256*20] k[256*20] v[256*28] psum[8*32] rinv[32] = 17696
#define SMEM_FLOATS (2 * (TT * XP1 + 2 * 16 * WSP))
#define SMEM_BYTES  (SMEM_FLOATS * 4)

__device__ __forceinline__ unsigned f2tf(float f) {
    unsigned r;
    asm("cvt.rna.tf32.f32 %0, %1;" : "=r"(r) : "f"(f));
    return r;
}

// pack two f32 into bf16x2: low half <- lo, high half <- hi
__device__ __forceinline__ unsigned pk2(float lo, float hi) {
    unsigned r;
    asm("cvt.rn.bf16x2.f32 %0, %1, %2;" : "=r"(r) : "f"(hi), "f"(lo));
    return r;
}
__device__ __forceinline__ float bflo(unsigned u) { return __uint_as_float(u << 16); }
__device__ __forceinline__ float bfhi(unsigned u) { return __uint_as_float(u & 0xffff0000u); }
// residual (lo-order) bf16x2 for 3-term split
__device__ __forceinline__ unsigned pkres(float lo, float hi, unsigned h) {
    return pk2(lo - bflo(h), hi - bfhi(h));
}

__device__ __forceinline__ void mma_tf32(float* c, const unsigned* a, const unsigned* b) {
    asm volatile(
        "mma.sync.aligned.m16n8k8.row.col.f32.tf32.tf32.f32 "
        "{%0,%1,%2,%3}, {%4,%5,%6,%7}, {%8,%9}, {%0,%1,%2,%3};"
        : "+f"(c[0]), "+f"(c[1]), "+f"(c[2]), "+f"(c[3])
        : "r"(a[0]), "r"(a[1]), "r"(a[2]), "r"(a[3]), "r"(b[0]), "r"(b[1]));
}

__device__ __forceinline__ void mma_bf16(float* c, const unsigned* a, const unsigned* b) {
    asm volatile(
        "mma.sync.aligned.m16n8k16.row.col.f32.bf16.bf16.f32 "
        "{%0,%1,%2,%3}, {%4,%5,%6,%7}, {%8,%9}, {%0,%1,%2,%3};"
        : "+f"(c[0]), "+f"(c[1]), "+f"(c[2]), "+f"(c[3])
        : "r"(a[0]), "r"(a[1]), "r"(a[2]), "r"(a[3]), "r"(b[0]), "r"(b[1]));
}

__device__ __forceinline__ void cpa16(uint32_t saddr, const float* g) {
    asm volatile("cp.async.ca.shared.global [%0], [%1], 16;" :: "r"(saddr), "l"(g));
}

__global__ void __launch_bounds__(256, 2) head_fused_kernel(
    const float* __restrict__ x,
    const float* __restrict__ wk,
    const float* __restrict__ wq,
    const float* __restrict__ wv,
    float* __restrict__ out)
{
    extern __shared__ float sm[];
    const int b    = blockIdx.x;
    const int tid  = threadIdx.x;
    const int lane = tid & 31;
    const int warp = tid >> 5;
    const int grp  = lane >> 2;  // 0..7
    const int tig  = lane & 3;   // 0..3

    const uint32_t sm_base = (uint32_t)__cvta_generic_to_shared(sm);

    // phase-2 smem views
    float* q_s  = sm;
    float* k_s  = q_s + TT * QKP;
    float* v_s  = k_s + TT * QKP;
    float* psum = v_s + TT * VPD;
    float* rinv = psum + 8 * 32;

    const float* xb = x + (size_t)b * TT * CC;

    // ================= Phase 1: qkv = x @ [Wq|Wk|Wv], bf16 3-term split ==========
    // x: cp.async raw fp32, split to bf16x2 hi/lo at fragment time.
    // W: cooperative LDG -> bf16x2 hi/lo packed STS (k-pairs packed per word).
    const int R = warp * 32;

    float acc[2][6][4];
#pragma unroll
    for (int mt = 0; mt < 2; ++mt)
#pragma unroll
        for (int nt = 0; nt < 6; ++nt)
#pragma unroll
            for (int e = 0; e < 4; ++e) acc[mt][nt][e] = 0.f;

    auto load_chunk = [&](int kc, int buf) {
        const float* xg = xb + kc * KCH;
        uint32_t xs_a = sm_base + (uint32_t)(buf * TT * XP1) * 4u;
#pragma unroll
        for (int i = 0; i < 8; ++i) {
            int row = (tid >> 3) + i * 32;
            int c4  = (tid & 7) * 4;
            cpa16(xs_a + (uint32_t)(row * XP1 + c4) * 4u, xg + row * CC + c4);
        }
        // W: packed bf16x2 hi/lo, word [kp][c] = {lo16: w[2kp][c], hi16: w[2kp+1][c]}
        unsigned* whd = reinterpret_cast<unsigned*>(sm + 2 * TT * XP1 + buf * 2 * 16 * WSP);
        unsigned* wld = whd + 16 * WSP;
#pragma unroll
        for (int i = 0; i < 3; ++i) {
            int f  = tid + i * 256;          // 768 word-pairs total
            int kp = f / 48, c = f % 48;
            int gk = kc * KCH + 2 * kp;
            const float* src = (c < 16) ? (wq + gk * HSZ + c)
                             : (c < 32) ? (wk + gk * HSZ + (c - 16))
                                        : (wv + gk * HSZ + (c - 32));
            float w0 = src[0];
            float w1 = src[HSZ];
            unsigned h = pk2(w0, w1);
            whd[kp * WSP + c] = h;
            wld[kp * WSP + c] = pkres(w0, w1, h);
        }
    };

    load_chunk(0, 0);
    asm volatile("cp.async.commit_group;");

    for (int kc = 0; kc < NKC; ++kc) {
        const int buf = kc & 1;
        if (kc + 1 < NKC) {
            load_chunk(kc + 1, buf ^ 1);
            asm volatile("cp.async.commit_group;");
            asm volatile("cp.async.wait_group 1;");
        } else {
            asm volatile("cp.async.wait_group 0;");
        }
        __syncthreads();

        const float* xs = sm + buf * TT * XP1;
        const unsigned* wh = reinterpret_cast<const unsigned*>(
            sm + 2 * TT * XP1 + buf * 2 * 16 * WSP);
        const unsigned* wl = wh + 16 * WSP;

#pragma unroll
        for (int ch = 0; ch < 2; ++ch) {          // two k16 chunks per kc
            const int ko = ch * 16;
            unsigned ah[2][4], al[2][4];
#pragma unroll
            for (int mt = 0; mt < 2; ++mt) {
                int r0 = R + mt * 16 + grp;
                float2 x0 = *reinterpret_cast<const float2*>(xs + r0 * XP1 + ko + 2 * tig);
                float2 x1 = *reinterpret_cast<const float2*>(xs + (r0 + 8) * XP1 + ko + 2 * tig);
                float2 x2 = *reinterpret_cast<const float2*>(xs + r0 * XP1 + ko + 8 + 2 * tig);
                float2 x3 = *reinterpret_cast<const float2*>(xs + (r0 + 8) * XP1 + ko + 8 + 2 * tig);
                ah[mt][0] = pk2(x0.x, x0.y); al[mt][0] = pkres(x0.x, x0.y, ah[mt][0]);
                ah[mt][1] = pk2(x1.x, x1.y); al[mt][1] = pkres(x1.x, x1.y, ah[mt][1]);
                ah[mt][2] = pk2(x2.x, x2.y); al[mt][2] = pkres(x2.x, x2.y, ah[mt][2]);
                ah[mt][3] = pk2(x3.x, x3.y); al[mt][3] = pkres(x3.x, x3.y, ah[mt][3]);
            }
#pragma unroll
            for (int nt = 0; nt < 6; ++nt) {
                int cb = nt * 8 + grp;
                unsigned bh[2], bl[2];
                bh[0] = wh[(ch * 8 + tig) * WSP + cb];
                bh[1] = wh[(ch * 8 + 4 + tig) * WSP + cb];
                bl[0] = wl[(ch * 8 + tig) * WSP + cb];
                bl[1] = wl[(ch * 8 + 4 + tig) * WSP + cb];
#pragma unroll
                for (int mt = 0; mt < 2; ++mt) {
                    mma_bf16(acc[mt][nt], ah[mt], bh);
                    mma_bf16(acc[mt][nt], ah[mt], bl);
                    mma_bf16(acc[mt][nt], al[mt], bh);
                }
            }
        }
        __syncthreads();
    }

    // scatter qkv; q (scaled) and k pre-rounded to tf32; v raw fp32
    const float qscale = rsqrtf((float)CC);
#pragma unroll
    for (int mt = 0; mt < 2; ++mt)
#pragma unroll
        for (int nt = 0; nt < 6; ++nt)
#pragma unroll
            for (int e = 0; e < 4; ++e) {
                int r   = R + mt * 16 + grp + ((e >= 2) ? 8 : 0);
                int cgl = nt * 8 + 2 * tig + (e & 1);
                float v = acc[mt][nt][e];
                if (cgl < 16)      q_s[r * QKP + cgl]        = __uint_as_float(f2tf(v * qscale));
                else if (cgl < 32) k_s[r * QKP + (cgl - 16)] = __uint_as_float(f2tf(v));
                else               v_s[r * VPD + (cgl - 32)] = v;
            }
    __syncthreads();

    // ================= Phase 2: attention, column softmax, balanced triangle ======
    const int rb0 = warp * 16;
    const int rb1 = 240 - warp * 16;
    int rb[2] = {rb0, rb1};

    float oacc[2][2][4];
#pragma unroll
    for (int mt = 0; mt < 2; ++mt)
#pragma unroll
        for (int nt = 0; nt < 2; ++nt)
#pragma unroll
            for (int e = 0; e < 4; ++e) oacc[mt][nt][e] = 0.f;

    for (int blk = 0; blk < TT / 32; ++blk) {
        const int s0 = blk * 32;
        const bool act0 = (warp >= 2 * blk);
        const bool act1 = ((15 - warp) >= 2 * blk);
        const bool anyact = act1;

        float ef[2][4][4];
#pragma unroll
        for (int mt = 0; mt < 2; ++mt)
#pragma unroll
            for (int nt = 0; nt < 4; ++nt)
#pragma unroll
                for (int e = 0; e < 4; ++e) ef[mt][nt][e] = 0.f;

        float ps[4][2];
#pragma unroll
        for (int nt = 0; nt < 4; ++nt) { ps[nt][0] = 0.f; ps[nt][1] = 0.f; }

        if (anyact) {
            // ---- S = q k^T (K=16), tf32, operands pre-rounded: raw LDS only ----
#pragma unroll
            for (int k8 = 0; k8 < 2; ++k8) {
                const int ko = k8 * 8;
                unsigned aq[2][4];
#pragma unroll
                for (int mt = 0; mt < 2; ++mt) {
                    if (mt == 0 && !act0) continue;
                    int r0 = rb[mt] + grp;
                    aq[mt][0] = __float_as_uint(q_s[r0 * QKP + ko + tig]);
                    aq[mt][1] = __float_as_uint(q_s[(r0 + 8) * QKP + ko + tig]);
                    aq[mt][2] = __float_as_uint(q_s[r0 * QKP + ko + tig + 4]);
                    aq[mt][3] = __float_as_uint(q_s[(r0 + 8) * QKP + ko + tig + 4]);
                }
#pragma unroll
                for (int nt = 0; nt < 4; ++nt) {
                    int sc = s0 + nt * 8 + grp;
                    unsigned bb[2];
                    bb[0] = __float_as_uint(k_s[sc * QKP + ko + tig]);
                    bb[1] = __float_as_uint(k_s[sc * QKP + ko + tig + 4]);
                    if (act0) mma_tf32(ef[0][nt], aq[0], bb);
                    mma_tf32(ef[1][nt], aq[1], bb);
                }
            }
            // ---- mask + exp (logits tiny; no max subtraction) ----
#pragma unroll
            for (int mt = 0; mt < 2; ++mt) {
                if (mt == 0 && !act0) {
#pragma unroll
                    for (int nt = 0; nt < 4; ++nt)
#pragma unroll
                        for (int e = 0; e < 4; ++e) ef[0][nt][e] = 0.f;
                    continue;
                }
#pragma unroll
                for (int nt = 0; nt < 4; ++nt)
#pragma unroll
                    for (int e = 0; e < 4; ++e) {
                        int r  = rb[mt] + grp + ((e >= 2) ? 8 : 0);
                        int sg = s0 + nt * 8 + 2 * tig + (e & 1);
                        ef[mt][nt][e] = (sg <= r) ? __expf(ef[mt][nt][e]) : 0.f;
                    }
            }
            // ---- per-column partial sums over this warp's 32 rows ----
#pragma unroll
            for (int nt = 0; nt < 4; ++nt)
#pragma unroll
                for (int bb2 = 0; bb2 < 2; ++bb2) {
                    float s = ef[0][nt][bb2] + ef[0][nt][bb2 + 2]
                            + ef[1][nt][bb2] + ef[1][nt][bb2 + 2];
                    s += __shfl_xor_sync(0xffffffffu, s, 4);
                    s += __shfl_xor_sync(0xffffffffu, s, 8);
                    s += __shfl_xor_sync(0xffffffffu, s, 16);
                    ps[nt][bb2] = s;
                }
        }
        if (grp == 0) {
#pragma unroll
            for (int nt = 0; nt < 4; ++nt) {
                psum[warp * 32 + nt * 8 + 2 * tig]     = ps[nt][0];
                psum[warp * 32 + nt * 8 + 2 * tig + 1] = ps[nt][1];
            }
        }
        __syncthreads();
        if (tid < 32) {
            float s = 0.f;
#pragma unroll
            for (int w = 0; w < 8; ++w) s += psum[w * 32 + tid];
            rinv[tid] = 1.0f / s;
        }
        __syncthreads();

        if (anyact) {
            // ---- PV in bf16 3-term, k16: C-frag of S == A-frag layout, NO shuffles
#pragma unroll
            for (int ch = 0; ch < 2; ++ch) {        // s-chunks of 16
                const int sb = s0 + ch * 16;
                unsigned pah[2][4], pal[2][4];
#pragma unroll
                for (int mt = 0; mt < 2; ++mt) {
                    if (mt == 0 && !act0) continue;
#pragma unroll
                    for (int hq = 0; hq < 2; ++hq) {  // k-halves -> S tiles 2ch, 2ch+1
                        float e0 = ef[mt][2 * ch + hq][0];
                        float e1 = ef[mt][2 * ch + hq][1];
                        float e2 = ef[mt][2 * ch + hq][2];
                        float e3 = ef[mt][2 * ch + hq][3];
                        pah[mt][2 * hq]     = pk2(e0, e1);
                        pal[mt][2 * hq]     = pkres(e0, e1, pah[mt][2 * hq]);
                        pah[mt][2 * hq + 1] = pk2(e2, e3);
                        pal[mt][2 * hq + 1] = pkres(e2, e3, pah[mt][2 * hq + 1]);
                    }
                }
                // NOTE: A-reg order: {0: rows grp k2t | 1: rows grp+8 k2t |
                //                     2: rows grp k8+2t | 3: rows grp+8 k8+2t}
                // built above as [2*hq], [2*hq+1] -> matches (hq=0 -> regs0,1; hq=1 -> 2,3)
                float r0 = rinv[ch * 16 + 2 * tig];
                float r1 = rinv[ch * 16 + 2 * tig + 1];
                float r2 = rinv[ch * 16 + 8 + 2 * tig];
                float r3 = rinv[ch * 16 + 9 + 2 * tig];
#pragma unroll
                for (int nt = 0; nt < 2; ++nt) {
                    int d = nt * 8 + grp;
                    float b0 = v_s[(sb + 2 * tig)     * VPD + d] * r0;
                    float b1 = v_s[(sb + 2 * tig + 1) * VPD + d] * r1;
                    float b2 = v_s[(sb + 8 + 2 * tig) * VPD + d] * r2;
                    float b3 = v_s[(sb + 9 + 2 * tig) * VPD + d] * r3;
                    unsigned bh[2], bl[2];
                    bh[0] = pk2(b0, b1); bl[0] = pkres(b0, b1, bh[0]);
                    bh[1] = pk2(b2, b3); bl[1] = pkres(b2, b3, bh[1]);
                    if (act0) {
                        mma_bf16(oacc[0][nt], pah[0], bh);
                        mma_bf16(oacc[0][nt], pah[0], bl);
                        mma_bf16(oacc[0][nt], pal[0], bh);
                    }
                    mma_bf16(oacc[1][nt], pah[1], bh);
                    mma_bf16(oacc[1][nt], pah[1], bl);
                    mma_bf16(oacc[1][nt], pal[1], bh);
                }
            }
        }
        // no trailing sync: next psum store (warp-local slot) is separated from
        // this block's rinv reads by the next iteration's first __syncthreads.
    }

    // ---- write out[b, t, d] ----
    float* ob = out + (size_t)b * TT * HSZ;
#pragma unroll
    for (int mt = 0; mt < 2; ++mt)
#pragma unroll
        for (int nt = 0; nt < 2; ++nt) {
            int r0 = rb[mt] + grp;
            int c  = nt * 8 + 2 * tig;
            *reinterpret_cast<float2*>(ob + r0 * HSZ + c) =
                make_float2(oacc[mt][nt][0], oacc[mt][nt][1]);
            *reinterpret_cast<float2*>(ob + (r0 + 8) * HSZ + c) =
                make_float2(oacc[mt][nt][2], oacc[mt][nt][3]);
        }
}

extern "C" void kernel_launch(void* const* d_in, const int* in_sizes, int n_in,
                              void* d_out, int out_size) {
    const float* x  = (const float*)d_in[0];
    const float* wk = (const float*)d_in[1];
    const float* wq = (const float*)d_in[2];
    const float* wv = (const float*)d_in[3];
    float* out      = (float*)d_out;

    const int B = in_sizes[0] / (TT * CC);  // 512

    cudaFuncSetAttribute(head_fused_kernel,
                         cudaFuncAttributeMaxDynamicSharedMemorySize, SMEM_BYTES);
    head_fused_kernel<<<B, 256, SMEM_BYTES>>>(x, wk, wq, wv, out);
}